// round 1
// baseline (speedup 1.0000x reference)
#include <cuda_runtime.h>
#include <math.h>

// ---------------- problem constants ----------------
#define BATCH   16
#define NSEQ    1024
#define HDIM    256
#define FDIM    400
#define ROWS    (BATCH * NSEQ)      // 16384
#define NHEADS  4
#define DH      64

// segments: pos[0,512) neg[512,768) frd[768,1024)
// scores scratch: 16*4*(512^2) + 2 * 16*4*(256^2)
#define SC_TOTAL 25165824L

// ---------------- static scratch (allowed; no allocs) ----------------
__device__ float g_t   [ROWS * HDIM];
__device__ float g_h1  [ROWS * HDIM];
__device__ float g_h2  [ROWS * HDIM];
__device__ float g_qkv [ROWS * 3 * HDIM];
__device__ float g_sc  [SC_TOTAL];
__device__ float g_ctx [ROWS * HDIM];
__device__ float g_proj[ROWS * HDIM];
__device__ float g_x1  [ROWS * HDIM];
__device__ float g_ff  [ROWS * FDIM];
__device__ float g_x2  [ROWS * HDIM];
__device__ float g_mean[3 * BATCH * HDIM];

// ---------------- generic tiled fp32 GEMM ----------------
// C[z] = scale * A[z] @ B[z] (+bias) (opt relu); optional row-gather on A; opt transB.
// Tile 64x64, BK=16, 256 threads, 4x4 microtile.
// Requirements used here: M % 64 == 0, K % 16 == 0, all leading dims % 4 == 0.
__global__ void gemm_k(const float* __restrict__ A, const float* __restrict__ Bm,
                       const float* __restrict__ bias, float* __restrict__ C,
                       int N, int K, int lda, int ldb, int ldc,
                       long soA, long siA, long soB, long siB, long soC, long siC,
                       int zinner, int transB, int doRelu, float scale,
                       const int* __restrict__ gidx)
{
    const int z  = blockIdx.z;
    const int zo = z / zinner, zi = z - zo * zinner;
    A  += zo * soA + zi * siA;
    Bm += zo * soB + zi * siB;
    C  += zo * soC + zi * siC;

    const int m0 = blockIdx.y * 64;
    const int n0 = blockIdx.x * 64;
    const int t  = threadIdx.x;

    __shared__ float As[16][64];
    __shared__ float Bs[16][64];

    const int ty = t >> 4, tx = t & 15;

    // A-tile load mapping: 64 rows x 16 k, float4 along k
    const int mA  = t >> 2;
    const int kqA = (t & 3) * 4;
    // B-tile (no trans): 16 k x 64 n, float4 along n
    const int kB = t >> 4;
    const int nB = (t & 15) * 4;
    // B-tile (trans): 64 n x 16 k, float4 along k
    const int nBt  = t >> 2;
    const int kqBt = (t & 3) * 4;

    long arow;
    if (gidx) arow = (long)gidx[m0 + mA] * lda;
    else      arow = (long)(m0 + mA) * lda;

    float acc[4][4] = {};

    for (int k0 = 0; k0 < K; k0 += 16) {
        float4 av = *(const float4*)(A + arow + k0 + kqA);
        As[kqA + 0][mA] = av.x;
        As[kqA + 1][mA] = av.y;
        As[kqA + 2][mA] = av.z;
        As[kqA + 3][mA] = av.w;

        if (!transB) {
            int col = n0 + nB;
            if (col + 3 < N) {
                *(float4*)&Bs[kB][nB] =
                    *(const float4*)(Bm + (long)(k0 + kB) * ldb + col);
            } else {
                #pragma unroll
                for (int q = 0; q < 4; q++)
                    Bs[kB][nB + q] = (col + q < N)
                        ? Bm[(long)(k0 + kB) * ldb + col + q] : 0.f;
            }
        } else {
            float4 bv = *(const float4*)(Bm + (long)(n0 + nBt) * ldb + k0 + kqBt);
            Bs[kqBt + 0][nBt] = bv.x;
            Bs[kqBt + 1][nBt] = bv.y;
            Bs[kqBt + 2][nBt] = bv.z;
            Bs[kqBt + 3][nBt] = bv.w;
        }
        __syncthreads();

        #pragma unroll
        for (int kk = 0; kk < 16; kk++) {
            float4 a = *(const float4*)&As[kk][ty * 4];
            float4 b = *(const float4*)&Bs[kk][tx * 4];
            acc[0][0] += a.x * b.x; acc[0][1] += a.x * b.y;
            acc[0][2] += a.x * b.z; acc[0][3] += a.x * b.w;
            acc[1][0] += a.y * b.x; acc[1][1] += a.y * b.y;
            acc[1][2] += a.y * b.z; acc[1][3] += a.y * b.w;
            acc[2][0] += a.z * b.x; acc[2][1] += a.z * b.y;
            acc[2][2] += a.z * b.z; acc[2][3] += a.z * b.w;
            acc[3][0] += a.w * b.x; acc[3][1] += a.w * b.y;
            acc[3][2] += a.w * b.z; acc[3][3] += a.w * b.w;
        }
        __syncthreads();
    }

    #pragma unroll
    for (int i = 0; i < 4; i++) {
        int row = m0 + ty * 4 + i;
        #pragma unroll
        for (int j = 0; j < 4; j++) {
            int col = n0 + tx * 4 + j;
            if (col < N) {
                float v = acc[i][j] * scale;
                if (bias)   v += bias[col];
                if (doRelu) v  = fmaxf(v, 0.f);
                C[(long)row * ldc + col] = v;
            }
        }
    }
}

// ---------------- row softmax over scores ----------------
__global__ void softmax_k(float* __restrict__ S, int L)
{
    long r = blockIdx.x;
    float* row = S + r * (long)L;
    int t = threadIdx.x;                 // 128 threads
    __shared__ float red[128];

    float m = -1e30f;
    for (int j = t; j < L; j += 128) m = fmaxf(m, row[j]);
    red[t] = m; __syncthreads();
    for (int s = 64; s > 0; s >>= 1) {
        if (t < s) red[t] = fmaxf(red[t], red[t + s]);
        __syncthreads();
    }
    m = red[0];
    __syncthreads();

    float sum = 0.f;
    for (int j = t; j < L; j += 128) {
        float e = expf(row[j] - m);
        row[j] = e;
        sum += e;
    }
    red[t] = sum; __syncthreads();
    for (int s = 64; s > 0; s >>= 1) {
        if (t < s) red[t] += red[t + s];
        __syncthreads();
    }
    float inv = 1.f / red[0];
    for (int j = t; j < L; j += 128) row[j] *= inv;
}

// ---------------- residual add + layernorm (H=256, 1 row/block) ----------------
__global__ void add_ln_k(const float* __restrict__ X, const float* __restrict__ R,
                         const float* __restrict__ g, const float* __restrict__ b,
                         float* __restrict__ O)
{
    int r = blockIdx.x, j = threadIdx.x;
    long base = (long)r * HDIM;
    float v = X[base + j] + R[base + j];

    __shared__ float red[HDIM];
    red[j] = v; __syncthreads();
    for (int s = 128; s > 0; s >>= 1) {
        if (j < s) red[j] += red[j + s];
        __syncthreads();
    }
    float mu = red[0] * (1.f / HDIM);
    __syncthreads();

    float d = v - mu;
    red[j] = d * d; __syncthreads();
    for (int s = 128; s > 0; s >>= 1) {
        if (j < s) red[j] += red[j + s];
        __syncthreads();
    }
    float var = red[0] * (1.f / HDIM);
    O[base + j] = d * rsqrtf(var + 1e-5f) * g[j] + b[j];
}

// ---------------- per-segment mean over sequence ----------------
__global__ void segmean_k(const float* __restrict__ X, float* __restrict__ Mo)
{
    int b = blockIdx.x, seg = blockIdx.y, j = threadIdx.x;
    const int off[3] = {0, 512, 768};
    const int len[3] = {512, 256, 256};
    int O = off[seg], L = len[seg];
    float s = 0.f;
    for (int i = 0; i < L; i++)
        s += X[(long)(b * NSEQ + O + i) * HDIM + j];
    Mo[(seg * BATCH + b) * HDIM + j] = s / (float)L;
}

// ---------------- out = relu((p - n + f) @ W + bias) ----------------
__global__ void final_k(const float* __restrict__ Mo, const float* __restrict__ W,
                        const float* __restrict__ bias, float* __restrict__ out)
{
    int b = blockIdx.x, j = threadIdx.x;
    __shared__ float comb[HDIM];
    comb[j] = Mo[(0 * BATCH + b) * HDIM + j]
            - Mo[(1 * BATCH + b) * HDIM + j]
            + Mo[(2 * BATCH + b) * HDIM + j];
    __syncthreads();
    float acc = bias[j];
    for (int k = 0; k < HDIM; k++)
        acc += comb[k] * W[k * HDIM + j];
    out[b * HDIM + j] = fmaxf(acc, 0.f);
}

// ---------------- host launcher ----------------
static inline void launch_gemm(const float* A, const float* Bm, const float* bias,
                               float* C, int M, int N, int K,
                               int lda, int ldb, int ldc,
                               long soA, long siA, long soB, long siB,
                               long soC, long siC, int zinner, int nz,
                               int transB, int doRelu, float scale, const int* gidx)
{
    dim3 grid((N + 63) / 64, M / 64, nz);
    gemm_k<<<grid, 256>>>(A, Bm, bias, C, N, K, lda, ldb, ldc,
                          soA, siA, soB, siB, soC, siC,
                          zinner, transB, doRelu, scale, gidx);
}

extern "C" void kernel_launch(void* const* d_in, const int* in_sizes, int n_in,
                              void* d_out, int out_size)
{
    const int*   idx   = (const int*)  d_in[0];
    const float* HT    = (const float*)d_in[1];
    const float* emb   = (const float*)d_in[2];
    const float* Wg1   = (const float*)d_in[3];
    const float* bg1   = (const float*)d_in[4];
    const float* Wg2   = (const float*)d_in[5];
    const float* bg2   = (const float*)d_in[6];
    const float* Wqkv  = (const float*)d_in[7];
    const float* bqkv  = (const float*)d_in[8];
    const float* Wo    = (const float*)d_in[9];
    const float* bo    = (const float*)d_in[10];
    const float* ln1g  = (const float*)d_in[11];
    const float* ln1b  = (const float*)d_in[12];
    const float* Wff1  = (const float*)d_in[13];
    const float* bff1  = (const float*)d_in[14];
    const float* Wff2  = (const float*)d_in[15];
    const float* bff2  = (const float*)d_in[16];
    const float* ln2g  = (const float*)d_in[17];
    const float* ln2b  = (const float*)d_in[18];
    const float* fc1W  = (const float*)d_in[19];
    const float* fc1b  = (const float*)d_in[20];
    // d_in[21..23] = n_acc/n_rej/n_frd scalars; baked in as 512/256/256.

    float *t, *h1, *h2, *qkv, *sc, *ctx, *proj, *x1, *ff, *x2, *mn;
    cudaGetSymbolAddress((void**)&t,    g_t);
    cudaGetSymbolAddress((void**)&h1,   g_h1);
    cudaGetSymbolAddress((void**)&h2,   g_h2);
    cudaGetSymbolAddress((void**)&qkv,  g_qkv);
    cudaGetSymbolAddress((void**)&sc,   g_sc);
    cudaGetSymbolAddress((void**)&ctx,  g_ctx);
    cudaGetSymbolAddress((void**)&proj, g_proj);
    cudaGetSymbolAddress((void**)&x1,   g_x1);
    cudaGetSymbolAddress((void**)&ff,   g_ff);
    cudaGetSymbolAddress((void**)&x2,   g_x2);
    cudaGetSymbolAddress((void**)&mn,   g_mean);

    // 1. t = emb[idx] @ Wg1                       (16384 x 256 x 256)
    launch_gemm(emb, Wg1, nullptr, t, ROWS, HDIM, HDIM, HDIM, HDIM, HDIM,
                0, 0, 0, 0, 0, 0, 1, 1, 0, 0, 1.f, idx);
    // 2. h1 = HT @ t + bg1   (batched 16x: 1024 x 256 x 1024)
    launch_gemm(HT, t, bg1, h1, NSEQ, HDIM, NSEQ, NSEQ, HDIM, HDIM,
                (long)NSEQ * NSEQ, 0, (long)NSEQ * HDIM, 0, (long)NSEQ * HDIM, 0,
                1, BATCH, 0, 0, 1.f, nullptr);
    // 3. t = h1 @ Wg2
    launch_gemm(h1, Wg2, nullptr, t, ROWS, HDIM, HDIM, HDIM, HDIM, HDIM,
                0, 0, 0, 0, 0, 0, 1, 1, 0, 0, 1.f, nullptr);
    // 4. h2 = HT @ t + bg2
    launch_gemm(HT, t, bg2, h2, NSEQ, HDIM, NSEQ, NSEQ, HDIM, HDIM,
                (long)NSEQ * NSEQ, 0, (long)NSEQ * HDIM, 0, (long)NSEQ * HDIM, 0,
                1, BATCH, 0, 0, 1.f, nullptr);
    // 5. qkv = h2 @ Wqkv + bqkv                  (16384 x 768 x 256)
    launch_gemm(h2, Wqkv, bqkv, qkv, ROWS, 3 * HDIM, HDIM, HDIM, 3 * HDIM, 3 * HDIM,
                0, 0, 0, 0, 0, 0, 1, 1, 0, 0, 1.f, nullptr);

    // 6. attention per segment (3-pass: scores GEMM, softmax, ctx GEMM)
    const int  off[3]   = {0, 512, 768};
    const int  len[3]   = {512, 256, 256};
    const long sbase[3] = {0L, 16777216L, 20971520L};
    for (int s = 0; s < 3; s++) {
        int  L  = len[s];
        long LL = (long)L * L;
        // scores[z=b*4+h] = Q @ K^T / 8   (L x L x 64), z: outer=b, inner=head
        launch_gemm(qkv + (long)off[s] * 768,        // Q base
                    qkv + (long)off[s] * 768 + 256,  // K base (transB)
                    nullptr, sc + sbase[s],
                    L, L, DH, 768, 768, L,
                    (long)NSEQ * 768, DH, (long)NSEQ * 768, DH, 4 * LL, LL,
                    NHEADS, BATCH * NHEADS, 1, 0, 0.125f, nullptr);
        softmax_k<<<BATCH * NHEADS * L, 128>>>(sc + sbase[s], L);
        // ctx = attn @ V   (L x 64 x L), written into ctx[:, h*64:(h+1)*64]
        launch_gemm(sc + sbase[s], qkv + (long)off[s] * 768 + 512, nullptr,
                    ctx + (long)off[s] * HDIM,
                    L, DH, L, L, 768, HDIM,
                    4 * LL, LL, (long)NSEQ * 768, DH, (long)NSEQ * HDIM, DH,
                    NHEADS, BATCH * NHEADS, 0, 0, 1.f, nullptr);
    }

    // 7. proj = ctx @ Wo + bo
    launch_gemm(ctx, Wo, bo, proj, ROWS, HDIM, HDIM, HDIM, HDIM, HDIM,
                0, 0, 0, 0, 0, 0, 1, 1, 0, 0, 1.f, nullptr);
    // 8. x1 = LN(h2 + proj)
    add_ln_k<<<ROWS, HDIM>>>(h2, proj, ln1g, ln1b, x1);
    // 9. ff = relu(x1 @ Wff1 + bff1)             (16384 x 400 x 256)
    launch_gemm(x1, Wff1, bff1, ff, ROWS, FDIM, HDIM, HDIM, FDIM, FDIM,
                0, 0, 0, 0, 0, 0, 1, 1, 0, 1, 1.f, nullptr);
    // 10. proj = ff @ Wff2 + bff2                (16384 x 256 x 400)
    launch_gemm(ff, Wff2, bff2, proj, ROWS, HDIM, FDIM, FDIM, HDIM, HDIM,
                0, 0, 0, 0, 0, 0, 1, 1, 0, 0, 1.f, nullptr);
    // 11. x2 = LN(x1 + proj)
    add_ln_k<<<ROWS, HDIM>>>(x1, proj, ln2g, ln2b, x2);
    // 12. segment means
    segmean_k<<<dim3(BATCH, 3), HDIM>>>(x2, mn);
    // 13. out = relu((p - n + f) @ fc1_W + fc1_b)
    final_k<<<BATCH, HDIM>>>(mn, fc1W, fc1b, (float*)d_out);
}

// round 2
// speedup vs baseline: 1.7747x; 1.7747x over previous
#include <cuda_runtime.h>
#include <math.h>
#include <stdint.h>

// ---------------- problem constants ----------------
#define BATCH   16
#define NSEQ    1024
#define HDIM    256
#define FDIM    400
#define ROWS    (BATCH * NSEQ)      // 16384
#define NHEADS  4
#define DH      64

// scores scratch: 16*4*(512^2) + 2 * 16*4*(256^2)
#define SC_TOTAL 25165824L

// ---------------- GEMM tiling ----------------
#define BM 128
#define BN 128
#define BK 32
#define ASTRIDE 36            // BK + 4 pad
#define BSTRIDE 132           // BN + 4 pad
#define ASZ (BM * ASTRIDE)    // 4608 words
#define BSZ (BK * BSTRIDE)    // 4224 words
#define BUFSZ (ASZ + BSZ)
#define GEMM_SMEM_BYTES (2 * BUFSZ * 4)   // 70656 B

// ---------------- static scratch ----------------
__device__ float g_t   [ROWS * HDIM];
__device__ float g_h1  [ROWS * HDIM];
__device__ float g_h2  [ROWS * HDIM];
__device__ float g_qkv [ROWS * 3 * HDIM];
__device__ float g_sc  [SC_TOTAL];
__device__ float g_ctx [ROWS * HDIM];
__device__ float g_proj[ROWS * HDIM];
__device__ float g_x1  [ROWS * HDIM];
__device__ float g_ff  [ROWS * FDIM];
__device__ float g_x2  [ROWS * HDIM];
__device__ float g_part[3 * BATCH * 8 * HDIM];   // segment partial sums

// ---------------- tf32 helpers ----------------
__device__ __forceinline__ uint32_t f2tf(float x) {
    uint32_t u; asm("cvt.rna.tf32.f32 %0, %1;" : "=r"(u) : "f"(x)); return u;
}

__device__ __forceinline__ void mma_tf32(float* c, const uint32_t* a, const uint32_t* b) {
    asm volatile(
        "mma.sync.aligned.m16n8k8.row.col.f32.tf32.tf32.f32 "
        "{%0,%1,%2,%3}, {%4,%5,%6,%7}, {%8,%9}, {%0,%1,%2,%3};"
        : "+f"(c[0]), "+f"(c[1]), "+f"(c[2]), "+f"(c[3])
        : "r"(a[0]), "r"(a[1]), "r"(a[2]), "r"(a[3]), "r"(b[0]), "r"(b[1]));
}

// ---------------- generic tf32 tensor-core GEMM ----------------
// C[z] = scale * A[z] @ B[z] (+bias)(relu); opt row-gather on A; opt transB.
// Requires M % 128 == 0, K % 4 == 0, lda/ldb multiples of 4. N arbitrary.
__global__ void __launch_bounds__(256, 1)
gemm_k(const float* __restrict__ A, const float* __restrict__ Bm,
       const float* __restrict__ bias, float* __restrict__ C,
       int N, int K, int lda, int ldb, int ldc,
       long soA, long siA, long soB, long siB, long soC, long siC,
       int zinner, int transB, int doRelu, float scale,
       const int* __restrict__ gidx)
{
    extern __shared__ uint32_t sh[];

    const int z  = blockIdx.z;
    const int zo = z / zinner, zi = z - zo * zinner;
    A  += zo * soA + zi * siA;
    Bm += zo * soB + zi * siB;
    C  += zo * soC + zi * siC;

    const int m0 = blockIdx.y * BM;
    const int n0 = blockIdx.x * BN;
    const int t    = threadIdx.x;
    const int lane = t & 31;
    const int w    = t >> 5;
    const int wm   = (w >> 2) * 64;   // warp m offset (0 or 64)
    const int wn   = (w & 3) * 32;    // warp n offset (0..96)
    const int r    = lane >> 2;       // groupID
    const int cc   = lane & 3;        // thread in group

    const int nk = (K + BK - 1) / BK;

    float pa[4][4];   // staged A loads (4 float4)
    float pb[4][4];   // staged B loads
    float acc[4][4][4] = {};

    // ---- staging helpers ----
    auto loadA = [&](int kt) {
        int k0 = kt * BK;
        #pragma unroll
        for (int i = 0; i < 4; i++) {
            int id = t + i * 256;
            int row = id >> 3, quad = id & 7;
            int gk = k0 + quad * 4;
            if (gk < K) {
                long arow = gidx ? (long)gidx[m0 + row] * lda
                                 : (long)(m0 + row) * lda;
                float4 v = *(const float4*)(A + arow + gk);
                pa[i][0] = v.x; pa[i][1] = v.y; pa[i][2] = v.z; pa[i][3] = v.w;
            } else {
                pa[i][0] = pa[i][1] = pa[i][2] = pa[i][3] = 0.f;
            }
        }
    };
    auto loadB = [&](int kt) {
        int k0 = kt * BK;
        if (!transB) {
            #pragma unroll
            for (int i = 0; i < 4; i++) {
                int id = t + i * 256;
                int kr = id >> 5, nq = id & 31;
                int gk = k0 + kr, gn = n0 + nq * 4;
                if (gk < K && gn + 3 < N) {
                    float4 v = *(const float4*)(Bm + (long)gk * ldb + gn);
                    pb[i][0] = v.x; pb[i][1] = v.y; pb[i][2] = v.z; pb[i][3] = v.w;
                } else {
                    #pragma unroll
                    for (int q = 0; q < 4; q++)
                        pb[i][q] = (gk < K && gn + q < N)
                                   ? Bm[(long)gk * ldb + gn + q] : 0.f;
                }
            }
        } else {
            #pragma unroll
            for (int i = 0; i < 4; i++) {
                int id = t + i * 256;
                int n = id >> 3, kq = id & 7;
                int gk = k0 + kq * 4, gn = n0 + n;
                if (gk < K && gn < N) {
                    float4 v = *(const float4*)(Bm + (long)gn * ldb + gk);
                    pb[i][0] = v.x; pb[i][1] = v.y; pb[i][2] = v.z; pb[i][3] = v.w;
                } else {
                    pb[i][0] = pb[i][1] = pb[i][2] = pb[i][3] = 0.f;
                }
            }
        }
    };
    auto storeA = [&](int buf) {
        uint32_t* As = sh + buf * BUFSZ;
        #pragma unroll
        for (int i = 0; i < 4; i++) {
            int id = t + i * 256;
            int row = id >> 3, quad = id & 7;
            uint4 u = make_uint4(f2tf(pa[i][0]), f2tf(pa[i][1]),
                                 f2tf(pa[i][2]), f2tf(pa[i][3]));
            *(uint4*)(As + row * ASTRIDE + quad * 4) = u;
        }
    };
    auto storeB = [&](int buf) {
        uint32_t* Bs = sh + buf * BUFSZ + ASZ;
        if (!transB) {
            #pragma unroll
            for (int i = 0; i < 4; i++) {
                int id = t + i * 256;
                int kr = id >> 5, nq = id & 31;
                uint4 u = make_uint4(f2tf(pb[i][0]), f2tf(pb[i][1]),
                                     f2tf(pb[i][2]), f2tf(pb[i][3]));
                *(uint4*)(Bs + kr * BSTRIDE + nq * 4) = u;
            }
        } else {
            #pragma unroll
            for (int i = 0; i < 4; i++) {
                int id = t + i * 256;
                int n = id >> 3, kq = id & 7;
                #pragma unroll
                for (int j = 0; j < 4; j++)
                    Bs[(kq * 4 + j) * BSTRIDE + n] = f2tf(pb[i][j]);
            }
        }
    };
    auto compute = [&](int buf) {
        const uint32_t* As = sh + buf * BUFSZ;
        const uint32_t* Bs = As + ASZ;
        #pragma unroll
        for (int k8 = 0; k8 < BK; k8 += 8) {
            uint32_t af[4][4], bf[4][2];
            #pragma unroll
            for (int mi = 0; mi < 4; mi++) {
                int rb = wm + mi * 16;
                af[mi][0] = As[(rb + r)     * ASTRIDE + k8 + cc];
                af[mi][1] = As[(rb + r + 8) * ASTRIDE + k8 + cc];
                af[mi][2] = As[(rb + r)     * ASTRIDE + k8 + cc + 4];
                af[mi][3] = As[(rb + r + 8) * ASTRIDE + k8 + cc + 4];
            }
            #pragma unroll
            for (int ni = 0; ni < 4; ni++) {
                int col = wn + ni * 8 + r;
                bf[ni][0] = Bs[(k8 + cc)     * BSTRIDE + col];
                bf[ni][1] = Bs[(k8 + cc + 4) * BSTRIDE + col];
            }
            #pragma unroll
            for (int mi = 0; mi < 4; mi++)
                #pragma unroll
                for (int ni = 0; ni < 4; ni++)
                    mma_tf32(acc[mi][ni], af[mi], bf[ni]);
        }
    };

    // ---- pipelined mainloop ----
    loadA(0); loadB(0);
    storeA(0); storeB(0);
    __syncthreads();
    for (int kt = 0; kt < nk; kt++) {
        int cur = kt & 1;
        if (kt + 1 < nk) { loadA(kt + 1); loadB(kt + 1); }
        compute(cur);
        if (kt + 1 < nk) { storeA(cur ^ 1); storeB(cur ^ 1); }
        __syncthreads();
    }

    // ---- epilogue ----
    #pragma unroll
    for (int mi = 0; mi < 4; mi++) {
        int row0 = m0 + wm + mi * 16 + r;
        #pragma unroll
        for (int ni = 0; ni < 4; ni++) {
            int col0 = n0 + wn + ni * 8 + 2 * cc;
            #pragma unroll
            for (int q = 0; q < 4; q++) {
                int row = row0 + (q >> 1) * 8;
                int col = col0 + (q & 1);
                if (col < N) {
                    float v = acc[mi][ni][q] * scale;
                    if (bias)   v += bias[col];
                    if (doRelu) v  = fmaxf(v, 0.f);
                    C[(long)row * ldc + col] = v;
                }
            }
        }
    }
}

// ---------------- row softmax over scores ----------------
__global__ void softmax_k(float* __restrict__ S, int L)
{
    long r = blockIdx.x;
    float* row = S + r * (long)L;
    int t = threadIdx.x;                 // 128 threads
    __shared__ float red[128];

    float m = -1e30f;
    for (int j = t; j < L; j += 128) m = fmaxf(m, row[j]);
    red[t] = m; __syncthreads();
    for (int s = 64; s > 0; s >>= 1) {
        if (t < s) red[t] = fmaxf(red[t], red[t + s]);
        __syncthreads();
    }
    m = red[0];
    __syncthreads();

    float sum = 0.f;
    for (int j = t; j < L; j += 128) {
        float e = expf(row[j] - m);
        row[j] = e;
        sum += e;
    }
    red[t] = sum; __syncthreads();
    for (int s = 64; s > 0; s >>= 1) {
        if (t < s) red[t] += red[t + s];
        __syncthreads();
    }
    float inv = 1.f / red[0];
    for (int j = t; j < L; j += 128) row[j] *= inv;
}

// ---------------- residual add + layernorm (H=256, 1 row/block) ----------------
__global__ void add_ln_k(const float* __restrict__ X, const float* __restrict__ R,
                         const float* __restrict__ g, const float* __restrict__ b,
                         float* __restrict__ O)
{
    int r = blockIdx.x, j = threadIdx.x;
    long base = (long)r * HDIM;
    float v = X[base + j] + R[base + j];

    __shared__ float red[HDIM];
    red[j] = v; __syncthreads();
    for (int s = 128; s > 0; s >>= 1) {
        if (j < s) red[j] += red[j + s];
        __syncthreads();
    }
    float mu = red[0] * (1.f / HDIM);
    __syncthreads();

    float d = v - mu;
    red[j] = d * d; __syncthreads();
    for (int s = 128; s > 0; s >>= 1) {
        if (j < s) red[j] += red[j + s];
        __syncthreads();
    }
    float var = red[0] * (1.f / HDIM);
    O[base + j] = d * rsqrtf(var + 1e-5f) * g[j] + b[j];
}

// ---------------- segment partial sums (chunked, deterministic) ----------------
__global__ void segpart_k(const float* __restrict__ X, float* __restrict__ P)
{
    int b = blockIdx.x, seg = blockIdx.y, chunk = blockIdx.z, j = threadIdx.x;
    const int off[3] = {0, 512, 768};
    const int len[3] = {512, 256, 256};
    int L = len[seg];
    int nch = L / 64;
    float s = 0.f;
    if (chunk < nch) {
        int base = b * NSEQ + off[seg] + chunk * 64;
        for (int i = 0; i < 64; i++)
            s += X[(long)(base + i) * HDIM + j];
    }
    P[(((seg * BATCH) + b) * 8 + chunk) * HDIM + j] = s;
}

// ---------------- out = relu((p - n + f) @ W + bias) ----------------
__global__ void final_k(const float* __restrict__ P, const float* __restrict__ W,
                        const float* __restrict__ bias, float* __restrict__ out)
{
    int b = blockIdx.x, j = threadIdx.x;
    __shared__ float comb[HDIM];
    float sp = 0.f, sn = 0.f, sf = 0.f;
    #pragma unroll
    for (int c = 0; c < 8; c++) {
        sp += P[((0 * BATCH + b) * 8 + c) * HDIM + j];
        sn += P[((1 * BATCH + b) * 8 + c) * HDIM + j];
        sf += P[((2 * BATCH + b) * 8 + c) * HDIM + j];
    }
    comb[j] = sp * (1.f / 512.f) - sn * (1.f / 256.f) + sf * (1.f / 256.f);
    __syncthreads();
    float acc = bias[j];
    for (int k = 0; k < HDIM; k++)
        acc += comb[k] * W[k * HDIM + j];
    out[b * HDIM + j] = fmaxf(acc, 0.f);
}

// ---------------- host launcher ----------------
static inline void launch_gemm(const float* A, const float* Bm, const float* bias,
                               float* C, int M, int N, int K,
                               int lda, int ldb, int ldc,
                               long soA, long siA, long soB, long siB,
                               long soC, long siC, int zinner, int nz,
                               int transB, int doRelu, float scale, const int* gidx)
{
    dim3 grid((N + BN - 1) / BN, M / BM, nz);
    gemm_k<<<grid, 256, GEMM_SMEM_BYTES>>>(A, Bm, bias, C, N, K, lda, ldb, ldc,
                                           soA, siA, soB, siB, soC, siC,
                                           zinner, transB, doRelu, scale, gidx);
}

extern "C" void kernel_launch(void* const* d_in, const int* in_sizes, int n_in,
                              void* d_out, int out_size)
{
    const int*   idx   = (const int*)  d_in[0];
    const float* HT    = (const float*)d_in[1];
    const float* emb   = (const float*)d_in[2];
    const float* Wg1   = (const float*)d_in[3];
    const float* bg1   = (const float*)d_in[4];
    const float* Wg2   = (const float*)d_in[5];
    const float* bg2   = (const float*)d_in[6];
    const float* Wqkv  = (const float*)d_in[7];
    const float* bqkv  = (const float*)d_in[8];
    const float* Wo    = (const float*)d_in[9];
    const float* bo    = (const float*)d_in[10];
    const float* ln1g  = (const float*)d_in[11];
    const float* ln1b  = (const float*)d_in[12];
    const float* Wff1  = (const float*)d_in[13];
    const float* bff1  = (const float*)d_in[14];
    const float* Wff2  = (const float*)d_in[15];
    const float* bff2  = (const float*)d_in[16];
    const float* ln2g  = (const float*)d_in[17];
    const float* ln2b  = (const float*)d_in[18];
    const float* fc1W  = (const float*)d_in[19];
    const float* fc1b  = (const float*)d_in[20];

    static int smem_set = 0;
    cudaFuncSetAttribute(gemm_k, cudaFuncAttributeMaxDynamicSharedMemorySize,
                         GEMM_SMEM_BYTES);
    (void)smem_set;

    float *t, *h1, *h2, *qkv, *sc, *ctx, *proj, *x1, *ff, *x2, *pp;
    cudaGetSymbolAddress((void**)&t,    g_t);
    cudaGetSymbolAddress((void**)&h1,   g_h1);
    cudaGetSymbolAddress((void**)&h2,   g_h2);
    cudaGetSymbolAddress((void**)&qkv,  g_qkv);
    cudaGetSymbolAddress((void**)&sc,   g_sc);
    cudaGetSymbolAddress((void**)&ctx,  g_ctx);
    cudaGetSymbolAddress((void**)&proj, g_proj);
    cudaGetSymbolAddress((void**)&x1,   g_x1);
    cudaGetSymbolAddress((void**)&ff,   g_ff);
    cudaGetSymbolAddress((void**)&x2,   g_x2);
    cudaGetSymbolAddress((void**)&pp,   g_part);

    // 1. t = emb[idx] @ Wg1
    launch_gemm(emb, Wg1, nullptr, t, ROWS, HDIM, HDIM, HDIM, HDIM, HDIM,
                0, 0, 0, 0, 0, 0, 1, 1, 0, 0, 1.f, idx);
    // 2. h1 = HT @ t + bg1
    launch_gemm(HT, t, bg1, h1, NSEQ, HDIM, NSEQ, NSEQ, HDIM, HDIM,
                (long)NSEQ * NSEQ, 0, (long)NSEQ * HDIM, 0, (long)NSEQ * HDIM, 0,
                1, BATCH, 0, 0, 1.f, nullptr);
    // 3. t = h1 @ Wg2
    launch_gemm(h1, Wg2, nullptr, t, ROWS, HDIM, HDIM, HDIM, HDIM, HDIM,
                0, 0, 0, 0, 0, 0, 1, 1, 0, 0, 1.f, nullptr);
    // 4. h2 = HT @ t + bg2
    launch_gemm(HT, t, bg2, h2, NSEQ, HDIM, NSEQ, NSEQ, HDIM, HDIM,
                (long)NSEQ * NSEQ, 0, (long)NSEQ * HDIM, 0, (long)NSEQ * HDIM, 0,
                1, BATCH, 0, 0, 1.f, nullptr);
    // 5. qkv = h2 @ Wqkv + bqkv
    launch_gemm(h2, Wqkv, bqkv, qkv, ROWS, 3 * HDIM, HDIM, HDIM, 3 * HDIM, 3 * HDIM,
                0, 0, 0, 0, 0, 0, 1, 1, 0, 0, 1.f, nullptr);

    // 6. attention per segment
    const int  off[3]   = {0, 512, 768};
    const int  len[3]   = {512, 256, 256};
    const long sbase[3] = {0L, 16777216L, 20971520L};
    for (int s = 0; s < 3; s++) {
        int  L  = len[s];
        long LL = (long)L * L;
        // scores = Q @ K^T / 8
        launch_gemm(qkv + (long)off[s] * 768,
                    qkv + (long)off[s] * 768 + 256,
                    nullptr, sc + sbase[s],
                    L, L, DH, 768, 768, L,
                    (long)NSEQ * 768, DH, (long)NSEQ * 768, DH, 4 * LL, LL,
                    NHEADS, BATCH * NHEADS, 1, 0, 0.125f, nullptr);
        softmax_k<<<BATCH * NHEADS * L, 128>>>(sc + sbase[s], L);
        // ctx = attn @ V
        launch_gemm(sc + sbase[s], qkv + (long)off[s] * 768 + 512, nullptr,
                    ctx + (long)off[s] * HDIM,
                    L, DH, L, L, 768, HDIM,
                    4 * LL, LL, (long)NSEQ * 768, DH, (long)NSEQ * HDIM, DH,
                    NHEADS, BATCH * NHEADS, 0, 0, 1.f, nullptr);
    }

    // 7. proj = ctx @ Wo + bo
    launch_gemm(ctx, Wo, bo, proj, ROWS, HDIM, HDIM, HDIM, HDIM, HDIM,
                0, 0, 0, 0, 0, 0, 1, 1, 0, 0, 1.f, nullptr);
    // 8. x1 = LN(h2 + proj)
    add_ln_k<<<ROWS, HDIM>>>(h2, proj, ln1g, ln1b, x1);
    // 9. ff = relu(x1 @ Wff1 + bff1)
    launch_gemm(x1, Wff1, bff1, ff, ROWS, FDIM, HDIM, HDIM, FDIM, FDIM,
                0, 0, 0, 0, 0, 0, 1, 1, 0, 1, 1.f, nullptr);
    // 10. proj = ff @ Wff2 + bff2
    launch_gemm(ff, Wff2, bff2, proj, ROWS, HDIM, FDIM, FDIM, HDIM, HDIM,
                0, 0, 0, 0, 0, 0, 1, 1, 0, 0, 1.f, nullptr);
    // 11. x2 = LN(x1 + proj)
    add_ln_k<<<ROWS, HDIM>>>(x1, proj, ln2g, ln2b, x2);
    // 12. segment partial sums + 13. final
    segpart_k<<<dim3(BATCH, 3, 8), HDIM>>>(x2, pp);
    final_k<<<BATCH, HDIM>>>(pp, fc1W, fc1b, (float*)d_out);
}

// round 3
// speedup vs baseline: 2.2933x; 1.2923x over previous
#include <cuda_runtime.h>
#include <math.h>
#include <stdint.h>

// ---------------- problem constants ----------------
#define BATCH   16
#define NSEQ    1024
#define HDIM    256
#define FDIM    400
#define ROWS    (BATCH * NSEQ)      // 16384
#define NHEADS  4
#define DH      64

#define SC_TOTAL 25165824L

// ---------------- static scratch ----------------
__device__ float g_t   [ROWS * HDIM];
__device__ float g_h1  [ROWS * HDIM];
__device__ float g_h2  [ROWS * HDIM];
__device__ float g_qkv [ROWS * 3 * HDIM];
__device__ float g_sc  [SC_TOTAL];
__device__ float g_ctx [ROWS * HDIM];
__device__ float g_proj[ROWS * HDIM];
__device__ float g_x1  [ROWS * HDIM];
__device__ float g_ff  [ROWS * FDIM];
__device__ float g_x2  [ROWS * HDIM];
__device__ float g_part[3 * BATCH * 8 * HDIM];

// ---------------- mma / cp.async helpers ----------------
__device__ __forceinline__ void mma_tf32(float* c, const uint32_t* a, const uint32_t* b) {
    asm volatile(
        "mma.sync.aligned.m16n8k8.row.col.f32.tf32.tf32.f32 "
        "{%0,%1,%2,%3}, {%4,%5,%6,%7}, {%8,%9}, {%0,%1,%2,%3};"
        : "+f"(c[0]), "+f"(c[1]), "+f"(c[2]), "+f"(c[3])
        : "r"(a[0]), "r"(a[1]), "r"(a[2]), "r"(a[3]), "r"(b[0]), "r"(b[1]));
}

__device__ __forceinline__ void cp16(uint32_t dst, const void* src, uint32_t bytes) {
    asm volatile("cp.async.cg.shared.global [%0], [%1], 16, %2;"
                 :: "r"(dst), "l"(src), "r"(bytes));
}
__device__ __forceinline__ void cp_commit() {
    asm volatile("cp.async.commit_group;");
}

// ---------------- generic tf32 tensor-core GEMM, cp.async 4-stage ----------------
// C[z] = scale * A[z] @ B[z] (+bias)(relu); opt row-gather on A; opt transB.
// BM=128 fixed, BK=32, BN_ template (128 or 64). M % 128 == 0, K % 4 == 0,
// N % 4 == 0, lda/ldb % 4 == 0.
#define BM 128
#define BK 32
#define STAGES 4

template<int BN_>
__global__ void __launch_bounds__(256, 1)
gemm_k(const float* __restrict__ A, const float* __restrict__ Bm,
       const float* __restrict__ bias, float* __restrict__ C,
       int N, int K, int lda, int ldb, int ldc,
       long soA, long siA, long soB, long siB, long soC, long siC,
       int zinner, int transB, int doRelu, float scale,
       const int* __restrict__ gidx)
{
    constexpr int ASTR  = BK + 4;           // 36
    constexpr int BNSTR = BN_ + 4;          // n-major stride (no-trans)
    constexpr int ASZ   = BM * ASTR;        // 4608 words
    constexpr int BSZ   = (BK * BNSTR > BN_ * ASTR) ? BK * BNSTR : BN_ * ASTR;
    constexpr int BUF   = ASZ + BSZ;        // words per stage
    constexpr int WCOLS = BN_ / 32;
    constexpr int WROWS = 8 / WCOLS;
    constexpr int WM    = BM / WROWS;
    constexpr int MI    = WM / 16;
    constexpr int BITER = BN_ / 32;         // cp.async iters for B

    extern __shared__ uint32_t sh[];
    const uint32_t shb = (uint32_t)__cvta_generic_to_shared(sh);

    const int z  = blockIdx.z;
    const int zo = z / zinner, zi = z - zo * zinner;
    A  += zo * soA + zi * siA;
    Bm += zo * soB + zi * siB;
    C  += zo * soC + zi * siC;

    const int m0 = blockIdx.y * BM;
    const int n0 = blockIdx.x * BN_;
    const int t    = threadIdx.x;
    const int lane = t & 31;
    const int w    = t >> 5;
    const int wm   = (w / WCOLS) * WM;
    const int wn   = (w % WCOLS) * 32;
    const int r    = lane >> 2;
    const int cc   = lane & 3;

    const int nk = (K + BK - 1) / BK;

    float acc[MI][4][4] = {};

    // ---- async loaders ----
    auto loadA = [&](int kt, int buf) {
        int k0 = kt * BK;
        uint32_t base = shb + (buf * BUF) * 4;
        #pragma unroll
        for (int i = 0; i < 4; i++) {
            int id  = t + i * 256;
            int row = id >> 3, ch = (id & 7) * 4;
            int gk  = k0 + ch;
            long arow = gidx ? (long)gidx[m0 + row] * lda
                             : (long)(m0 + row) * lda;
            const float* src = A + arow + (gk < K ? gk : 0);
            cp16(base + (row * ASTR + ch) * 4, src, (gk < K) ? 16u : 0u);
        }
    };
    auto loadB = [&](int kt, int buf) {
        int k0 = kt * BK;
        uint32_t base = shb + (buf * BUF + ASZ) * 4;
        if (!transB) {
            #pragma unroll
            for (int i = 0; i < BITER; i++) {
                int id = t + i * 256;
                int kr = id / (BN_ / 4), nq = (id % (BN_ / 4)) * 4;
                int gk = k0 + kr, gn = n0 + nq;
                bool ok = (gk < K) && (gn < N);
                const float* src = Bm + (ok ? ((long)gk * ldb + gn) : 0);
                cp16(base + (kr * BNSTR + nq) * 4, src, ok ? 16u : 0u);
            }
        } else {
            #pragma unroll
            for (int i = 0; i < BITER; i++) {
                int id = t + i * 256;
                int n = id >> 3, kq = (id & 7) * 4;
                int gk = k0 + kq, gn = n0 + n;
                bool ok = (gk < K) && (gn < N);
                const float* src = Bm + (ok ? ((long)gn * ldb + gk) : 0);
                cp16(base + (n * ASTR + kq) * 4, src, ok ? 16u : 0u);
            }
        }
    };

    auto compute = [&](int buf) {
        const uint32_t* As = sh + buf * BUF;
        const uint32_t* Bs = As + ASZ;
        #pragma unroll
        for (int k8 = 0; k8 < BK; k8 += 8) {
            uint32_t af[MI][4], bf[4][2];
            #pragma unroll
            for (int mi = 0; mi < MI; mi++) {
                int rb = wm + mi * 16;
                af[mi][0] = As[(rb + r)     * ASTR + k8 + cc];
                af[mi][1] = As[(rb + r + 8) * ASTR + k8 + cc];
                af[mi][2] = As[(rb + r)     * ASTR + k8 + cc + 4];
                af[mi][3] = As[(rb + r + 8) * ASTR + k8 + cc + 4];
            }
            if (!transB) {
                #pragma unroll
                for (int ni = 0; ni < 4; ni++) {
                    int col = wn + ni * 8 + r;
                    bf[ni][0] = Bs[(k8 + cc)     * BNSTR + col];
                    bf[ni][1] = Bs[(k8 + cc + 4) * BNSTR + col];
                }
            } else {
                #pragma unroll
                for (int ni = 0; ni < 4; ni++) {
                    int col = wn + ni * 8 + r;
                    bf[ni][0] = Bs[col * ASTR + k8 + cc];
                    bf[ni][1] = Bs[col * ASTR + k8 + cc + 4];
                }
            }
            #pragma unroll
            for (int mi = 0; mi < MI; mi++)
                #pragma unroll
                for (int ni = 0; ni < 4; ni++)
                    mma_tf32(acc[mi][ni], af[mi], bf[ni]);
        }
    };

    // ---- prologue: issue STAGES-1 stages ----
    #pragma unroll
    for (int s = 0; s < STAGES - 1; s++) {
        if (s < nk) { loadA(s, s); loadB(s, s); }
        cp_commit();
    }

    // ---- mainloop ----
    for (int kt = 0; kt < nk; kt++) {
        asm volatile("cp.async.wait_group %0;" :: "n"(STAGES - 2));
        __syncthreads();
        int nxt = kt + STAGES - 1;
        if (nxt < nk) { loadA(nxt, nxt % STAGES); loadB(nxt, nxt % STAGES); }
        cp_commit();
        compute(kt % STAGES);
    }

    // ---- epilogue ----
    #pragma unroll
    for (int mi = 0; mi < MI; mi++) {
        int row0 = m0 + wm + mi * 16 + r;
        #pragma unroll
        for (int ni = 0; ni < 4; ni++) {
            int col0 = n0 + wn + ni * 8 + 2 * cc;
            #pragma unroll
            for (int q = 0; q < 4; q++) {
                int row = row0 + (q >> 1) * 8;
                int col = col0 + (q & 1);
                if (col < N) {
                    float v = acc[mi][ni][q] * scale;
                    if (bias)   v += bias[col];
                    if (doRelu) v  = fmaxf(v, 0.f);
                    C[(long)row * ldc + col] = v;
                }
            }
        }
    }
}

// ---------------- single-pass register softmax (L = 256 or 512) ----------------
__global__ void softmax_k(float* __restrict__ S, int L)
{
    long rIdx = blockIdx.x;
    float* row = S + rIdx * (long)L;
    int t = threadIdx.x;                 // 256
    __shared__ float red[8];

    float v0 = row[t];
    float v1 = (L == 512) ? row[t + 256] : -1e30f;

    float m = fmaxf(v0, v1);
    #pragma unroll
    for (int o = 16; o; o >>= 1) m = fmaxf(m, __shfl_xor_sync(~0u, m, o));
    if ((t & 31) == 0) red[t >> 5] = m;
    __syncthreads();
    m = red[0];
    #pragma unroll
    for (int i = 1; i < 8; i++) m = fmaxf(m, red[i]);
    __syncthreads();

    float e0 = __expf(v0 - m);
    float e1 = (L == 512) ? __expf(v1 - m) : 0.f;
    float s = e0 + e1;
    #pragma unroll
    for (int o = 16; o; o >>= 1) s += __shfl_xor_sync(~0u, s, o);
    if ((t & 31) == 0) red[t >> 5] = s;
    __syncthreads();
    s = red[0];
    #pragma unroll
    for (int i = 1; i < 8; i++) s += red[i];

    float inv = 1.f / s;
    row[t] = e0 * inv;
    if (L == 512) row[t + 256] = e1 * inv;
}

// ---------------- residual add + layernorm (H=256) ----------------
__global__ void add_ln_k(const float* __restrict__ X, const float* __restrict__ R,
                         const float* __restrict__ g, const float* __restrict__ b,
                         float* __restrict__ O)
{
    int rI = blockIdx.x, j = threadIdx.x;
    long base = (long)rI * HDIM;
    float v = X[base + j] + R[base + j];
    __shared__ float red[8];

    float s = v;
    #pragma unroll
    for (int o = 16; o; o >>= 1) s += __shfl_xor_sync(~0u, s, o);
    if ((j & 31) == 0) red[j >> 5] = s;
    __syncthreads();
    s = red[0];
    #pragma unroll
    for (int i = 1; i < 8; i++) s += red[i];
    float mu = s * (1.f / HDIM);
    __syncthreads();

    float d = v - mu;
    float q = d * d;
    #pragma unroll
    for (int o = 16; o; o >>= 1) q += __shfl_xor_sync(~0u, q, o);
    if ((j & 31) == 0) red[j >> 5] = q;
    __syncthreads();
    q = red[0];
    #pragma unroll
    for (int i = 1; i < 8; i++) q += red[i];
    float var = q * (1.f / HDIM);

    O[base + j] = d * rsqrtf(var + 1e-5f) * g[j] + b[j];
}

// ---------------- segment partial sums ----------------
__global__ void segpart_k(const float* __restrict__ X, float* __restrict__ P)
{
    int b = blockIdx.x, seg = blockIdx.y, chunk = blockIdx.z, j = threadIdx.x;
    const int off[3] = {0, 512, 768};
    const int len[3] = {512, 256, 256};
    int L = len[seg];
    int nch = L / 64;
    float s = 0.f;
    if (chunk < nch) {
        int base = b * NSEQ + off[seg] + chunk * 64;
        for (int i = 0; i < 64; i++)
            s += X[(long)(base + i) * HDIM + j];
    }
    P[(((seg * BATCH) + b) * 8 + chunk) * HDIM + j] = s;
}

// ---------------- out = relu((p - n + f) @ W + bias) ----------------
__global__ void final_k(const float* __restrict__ P, const float* __restrict__ W,
                        const float* __restrict__ bias, float* __restrict__ out)
{
    int b = blockIdx.x, j = threadIdx.x;
    __shared__ float comb[HDIM];
    float sp = 0.f, sn = 0.f, sf = 0.f;
    #pragma unroll
    for (int c = 0; c < 8; c++) {
        sp += P[((0 * BATCH + b) * 8 + c) * HDIM + j];
        sn += P[((1 * BATCH + b) * 8 + c) * HDIM + j];
        sf += P[((2 * BATCH + b) * 8 + c) * HDIM + j];
    }
    comb[j] = sp * (1.f / 512.f) - sn * (1.f / 256.f) + sf * (1.f / 256.f);
    __syncthreads();
    float acc = bias[j];
    for (int k = 0; k < HDIM; k++)
        acc += comb[k] * W[k * HDIM + j];
    out[b * HDIM + j] = fmaxf(acc, 0.f);
}

// ---------------- host launcher ----------------
template<int BN_>
static inline void launch_gemm(const float* A, const float* Bm, const float* bias,
                               float* C, int M, int N, int K,
                               int lda, int ldb, int ldc,
                               long soA, long siA, long soB, long siB,
                               long soC, long siC, int zinner, int nz,
                               int transB, int doRelu, float scale, const int* gidx)
{
    constexpr int ASTR  = BK + 4;
    constexpr int BNSTR = BN_ + 4;
    constexpr int ASZ   = BM * ASTR;
    constexpr int BSZ   = (BK * BNSTR > BN_ * ASTR) ? BK * BNSTR : BN_ * ASTR;
    constexpr int SMEM  = STAGES * (ASZ + BSZ) * 4;
    dim3 grid((N + BN_ - 1) / BN_, M / BM, nz);
    gemm_k<BN_><<<grid, 256, SMEM>>>(A, Bm, bias, C, N, K, lda, ldb, ldc,
                                     soA, siA, soB, siB, soC, siC,
                                     zinner, transB, doRelu, scale, gidx);
}

extern "C" void kernel_launch(void* const* d_in, const int* in_sizes, int n_in,
                              void* d_out, int out_size)
{
    const int*   idx   = (const int*)  d_in[0];
    const float* HT    = (const float*)d_in[1];
    const float* emb   = (const float*)d_in[2];
    const float* Wg1   = (const float*)d_in[3];
    const float* bg1   = (const float*)d_in[4];
    const float* Wg2   = (const float*)d_in[5];
    const float* bg2   = (const float*)d_in[6];
    const float* Wqkv  = (const float*)d_in[7];
    const float* bqkv  = (const float*)d_in[8];
    const float* Wo    = (const float*)d_in[9];
    const float* bo    = (const float*)d_in[10];
    const float* ln1g  = (const float*)d_in[11];
    const float* ln1b  = (const float*)d_in[12];
    const float* Wff1  = (const float*)d_in[13];
    const float* bff1  = (const float*)d_in[14];
    const float* Wff2  = (const float*)d_in[15];
    const float* bff2  = (const float*)d_in[16];
    const float* ln2g  = (const float*)d_in[17];
    const float* ln2b  = (const float*)d_in[18];
    const float* fc1W  = (const float*)d_in[19];
    const float* fc1b  = (const float*)d_in[20];

    {
        constexpr int S128 = STAGES * (BM*(BK+4) + BM*(BK+4)) * 4; // ASZ==BSZ for BN128
        constexpr int S64  = STAGES * (BM*(BK+4) + 64*(BK+4)) * 4;
        cudaFuncSetAttribute(gemm_k<128>,
            cudaFuncAttributeMaxDynamicSharedMemorySize, S128);
        cudaFuncSetAttribute(gemm_k<64>,
            cudaFuncAttributeMaxDynamicSharedMemorySize, S64);
    }

    float *t, *h1, *h2, *qkv, *sc, *ctx, *proj, *x1, *ff, *x2, *pp;
    cudaGetSymbolAddress((void**)&t,    g_t);
    cudaGetSymbolAddress((void**)&h1,   g_h1);
    cudaGetSymbolAddress((void**)&h2,   g_h2);
    cudaGetSymbolAddress((void**)&qkv,  g_qkv);
    cudaGetSymbolAddress((void**)&sc,   g_sc);
    cudaGetSymbolAddress((void**)&ctx,  g_ctx);
    cudaGetSymbolAddress((void**)&proj, g_proj);
    cudaGetSymbolAddress((void**)&x1,   g_x1);
    cudaGetSymbolAddress((void**)&ff,   g_ff);
    cudaGetSymbolAddress((void**)&x2,   g_x2);
    cudaGetSymbolAddress((void**)&pp,   g_part);

    // 1. t = emb[idx] @ Wg1
    launch_gemm<128>(emb, Wg1, nullptr, t, ROWS, HDIM, HDIM, HDIM, HDIM, HDIM,
                     0, 0, 0, 0, 0, 0, 1, 1, 0, 0, 1.f, idx);
    // 2. h1 = HT @ t + bg1
    launch_gemm<128>(HT, t, bg1, h1, NSEQ, HDIM, NSEQ, NSEQ, HDIM, HDIM,
                     (long)NSEQ*NSEQ, 0, (long)NSEQ*HDIM, 0, (long)NSEQ*HDIM, 0,
                     1, BATCH, 0, 0, 1.f, nullptr);
    // 3. t = h1 @ Wg2
    launch_gemm<128>(h1, Wg2, nullptr, t, ROWS, HDIM, HDIM, HDIM, HDIM, HDIM,
                     0, 0, 0, 0, 0, 0, 1, 1, 0, 0, 1.f, nullptr);
    // 4. h2 = HT @ t + bg2
    launch_gemm<128>(HT, t, bg2, h2, NSEQ, HDIM, NSEQ, NSEQ, HDIM, HDIM,
                     (long)NSEQ*NSEQ, 0, (long)NSEQ*HDIM, 0, (long)NSEQ*HDIM, 0,
                     1, BATCH, 0, 0, 1.f, nullptr);
    // 5. qkv = h2 @ Wqkv + bqkv
    launch_gemm<128>(h2, Wqkv, bqkv, qkv, ROWS, 3*HDIM, HDIM, HDIM, 3*HDIM, 3*HDIM,
                     0, 0, 0, 0, 0, 0, 1, 1, 0, 0, 1.f, nullptr);

    // 6. attention per segment
    const int  off[3]   = {0, 512, 768};
    const int  len[3]   = {512, 256, 256};
    const long sbase[3] = {0L, 16777216L, 20971520L};
    for (int s = 0; s < 3; s++) {
        int  L  = len[s];
        long LL = (long)L * L;
        // scores = Q @ K^T / 8
        launch_gemm<128>(qkv + (long)off[s] * 768,
                         qkv + (long)off[s] * 768 + 256,
                         nullptr, sc + sbase[s],
                         L, L, DH, 768, 768, L,
                         (long)NSEQ*768, DH, (long)NSEQ*768, DH, 4*LL, LL,
                         NHEADS, BATCH*NHEADS, 1, 0, 0.125f, nullptr);
        softmax_k<<<BATCH * NHEADS * L, 256>>>(sc + sbase[s], L);
        // ctx = attn @ V   (N=64 -> BN64 variant)
        launch_gemm<64>(sc + sbase[s], qkv + (long)off[s] * 768 + 512, nullptr,
                        ctx + (long)off[s] * HDIM,
                        L, DH, L, L, 768, HDIM,
                        4*LL, LL, (long)NSEQ*768, DH, (long)NSEQ*HDIM, DH,
                        NHEADS, BATCH*NHEADS, 0, 0, 1.f, nullptr);
    }

    // 7. proj = ctx @ Wo + bo
    launch_gemm<128>(ctx, Wo, bo, proj, ROWS, HDIM, HDIM, HDIM, HDIM, HDIM,
                     0, 0, 0, 0, 0, 0, 1, 1, 0, 0, 1.f, nullptr);
    // 8. x1 = LN(h2 + proj)
    add_ln_k<<<ROWS, HDIM>>>(h2, proj, ln1g, ln1b, x1);
    // 9. ff = relu(x1 @ Wff1 + bff1)
    launch_gemm<128>(x1, Wff1, bff1, ff, ROWS, FDIM, HDIM, HDIM, FDIM, FDIM,
                     0, 0, 0, 0, 0, 0, 1, 1, 0, 1, 1.f, nullptr);
    // 10. proj = ff @ Wff2 + bff2
    launch_gemm<128>(ff, Wff2, bff2, proj, ROWS, HDIM, FDIM, FDIM, HDIM, HDIM,
                     0, 0, 0, 0, 0, 0, 1, 1, 0, 0, 1.f, nullptr);
    // 11. x2 = LN(x1 + proj)
    add_ln_k<<<ROWS, HDIM>>>(x1, proj, ln2g, ln2b, x2);
    // 12./13. segment means + final fc
    segpart_k<<<dim3(BATCH, 3, 8), HDIM>>>(x2, pp);
    final_k<<<BATCH, HDIM>>>(pp, fc1W, fc1b, (float*)d_out);
}